// round 1
// baseline (speedup 1.0000x reference)
#include <cuda_runtime.h>
#include <cstdint>
#include <cstddef>

#define BB 64
#define LL 1024
#define II 256
#define HH 512
#define GRID_R 128
#define THR_R 256

// Scratch (device globals -- no allocation allowed in kernel_launch)
__device__ __align__(16) float g_X[(size_t)LL * 3 * HH * BB];   // [t][gate][f][b]
__device__ __align__(16) float g_H[2][HH * BB];                 // [kq][b][4] quad-of-features layout
__device__ unsigned g_cnt;
__device__ unsigned g_gen;

// ---------- packed f32x2 helpers (sm_103a) ----------
__device__ __forceinline__ unsigned long long pack2(float x, float y) {
    unsigned long long r;
    asm("mov.b64 %0, {%1,%2};" : "=l"(r) : "f"(x), "f"(y));
    return r;
}
__device__ __forceinline__ float2 unpack2(unsigned long long v) {
    float2 r;
    asm("mov.b64 {%0,%1}, %2;" : "=f"(r.x), "=f"(r.y) : "l"(v));
    return r;
}
__device__ __forceinline__ void ffma2(unsigned long long& d, unsigned long long a, unsigned long long b) {
    asm("fma.rn.f32x2 %0, %1, %2, %0;" : "+l"(d) : "l"(a), "l"(b));
}
// 16B L2-only load (h is rewritten by other SMs each step; L1 is not coherent)
__device__ __forceinline__ ulonglong2 ldcg128(const void* p) {
    ulonglong2 v;
    asm volatile("ld.global.cg.v2.u64 {%0,%1}, [%2];"
                 : "=l"(v.x), "=l"(v.y) : "l"(p));
    return v;
}
__device__ __forceinline__ float ldcg32(const float* p) {
    float v;
    asm volatile("ld.global.cg.f32 %0, [%1];" : "=f"(v) : "l"(p));
    return v;
}

__device__ __forceinline__ float sigf(float x) {
    return 1.0f / (1.0f + __expf(-x));
}
__device__ __forceinline__ float tanh_f(float x) {
    x = fminf(15.0f, fmaxf(-15.0f, x));
    float e = __expf(-2.0f * x);
    return (1.0f - e) / (1.0f + e);
}

// ---------- software grid barrier (all GRID_R CTAs co-resident) ----------
__device__ __forceinline__ void grid_bar(int tid, unsigned& mygen) {
    __syncthreads();
    if (tid == 0) {
        __threadfence();
        ++mygen;
        if (atomicAdd(&g_cnt, 1u) == GRID_R - 1) {
            atomicExch(&g_cnt, 0u);
            __threadfence();
            atomicExch(&g_gen, mygen);
        } else {
            while (*((volatile unsigned*)&g_gen) != mygen) { }
        }
        __threadfence();
    }
    __syncthreads();
}

// ============================================================
// Kernel 1: fused input projections  X[t][g][f][b] = inputs @ W_i{r,z,n}^T + b_i
// Tile: 128 (rows of W) x 64 (all batches, one t), K=256. f32x2 packed FMA.
// ============================================================
__global__ __launch_bounds__(256) void input_proj_kernel(
    const float* __restrict__ inp,
    const float* __restrict__ wir, const float* __restrict__ wiz, const float* __restrict__ win,
    const float* __restrict__ bir, const float* __restrict__ biz, const float* __restrict__ bin)
{
    const int t  = blockIdx.x;
    const int mt = blockIdx.y;                 // 0..11
    const int gate  = mt >> 2;
    const int frow0 = (mt & 3) * 128;
    const float* __restrict__ W  = (gate == 0) ? wir : ((gate == 1) ? wiz : win);
    const float* __restrict__ bi = (gate == 0) ? bir : ((gate == 1) ? biz : bin);

    __shared__ __align__(16) float As[32][132];   // [k][m], padded
    __shared__ __align__(16) float Bs[32][68];    // [k][n], padded

    const int tid = threadIdx.x;
    const int tx = tid & 15;   // n-group: 4 cols
    const int ty = tid >> 4;   // m-group: 8 rows (4 f32x2 pairs)

    unsigned long long acc[4][4];
#pragma unroll
    for (int p = 0; p < 4; ++p)
#pragma unroll
        for (int q = 0; q < 4; ++q) acc[p][q] = 0ull;   // bits(0,0) == (0.f,0.f)

    const int akg  = tid & 7;    // k-quad 0..7
    const int arow = tid >> 3;   // 0..31
    const int bbi  = tid >> 2;   // 0..63
    const int bkq  = tid & 3;

    for (int kc = 0; kc < II; kc += 32) {
        // A tile: W[frow0..+128][kc..kc+32] -> As[k][m]
#pragma unroll
        for (int it = 0; it < 4; ++it) {
            int r = arow + 32 * it;
            float4 v = *(const float4*)&W[(size_t)(frow0 + r) * II + kc + akg * 4];
            As[akg * 4 + 0][r] = v.x; As[akg * 4 + 1][r] = v.y;
            As[akg * 4 + 2][r] = v.z; As[akg * 4 + 3][r] = v.w;
        }
        // B tile: inputs[b][t][kc..kc+32] -> Bs[k][b]
#pragma unroll
        for (int it = 0; it < 2; ++it) {
            int k0 = bkq * 4 + it * 16;
            float4 v = *(const float4*)&inp[((size_t)bbi * LL + t) * II + kc + k0];
            Bs[k0 + 0][bbi] = v.x; Bs[k0 + 1][bbi] = v.y;
            Bs[k0 + 2][bbi] = v.z; Bs[k0 + 3][bbi] = v.w;
        }
        __syncthreads();
#pragma unroll
        for (int k = 0; k < 32; ++k) {
            const ulonglong2 a01 = *(const ulonglong2*)&As[k][ty * 8];
            const ulonglong2 a23 = *(const ulonglong2*)&As[k][ty * 8 + 4];
            const float4 bv = *(const float4*)&Bs[k][tx * 4];
            unsigned long long b0 = pack2(bv.x, bv.x);
            unsigned long long b1 = pack2(bv.y, bv.y);
            unsigned long long b2 = pack2(bv.z, bv.z);
            unsigned long long b3 = pack2(bv.w, bv.w);
            ffma2(acc[0][0], a01.x, b0); ffma2(acc[0][1], a01.x, b1);
            ffma2(acc[0][2], a01.x, b2); ffma2(acc[0][3], a01.x, b3);
            ffma2(acc[1][0], a01.y, b0); ffma2(acc[1][1], a01.y, b1);
            ffma2(acc[1][2], a01.y, b2); ffma2(acc[1][3], a01.y, b3);
            ffma2(acc[2][0], a23.x, b0); ffma2(acc[2][1], a23.x, b1);
            ffma2(acc[2][2], a23.x, b2); ffma2(acc[2][3], a23.x, b3);
            ffma2(acc[3][0], a23.y, b0); ffma2(acc[3][1], a23.y, b1);
            ffma2(acc[3][2], a23.y, b2); ffma2(acc[3][3], a23.y, b3);
        }
        __syncthreads();
    }

    float* __restrict__ Xout = g_X + (size_t)(t * 3 + gate) * HH * BB;
#pragma unroll
    for (int p = 0; p < 4; ++p) {
        float2 c0 = unpack2(acc[p][0]);
        float2 c1 = unpack2(acc[p][1]);
        float2 c2 = unpack2(acc[p][2]);
        float2 c3 = unpack2(acc[p][3]);
        int r0 = frow0 + ty * 8 + 2 * p;
        float be0 = bi[r0], be1 = bi[r0 + 1];
        float4 o0 = make_float4(c0.x + be0, c1.x + be0, c2.x + be0, c3.x + be0);
        float4 o1 = make_float4(c0.y + be1, c1.y + be1, c2.y + be1, c3.y + be1);
        *(float4*)&Xout[(size_t)r0 * BB + tx * 4]       = o0;
        *(float4*)&Xout[(size_t)(r0 + 1) * BB + tx * 4] = o1;
    }
}

// ============================================================
// Kernel 2: persistent GRU scan. 128 CTAs x 256 threads.
// CTA g owns hidden features [4g, 4g+4); its 3x4x512 recurrent weight slice
// lives in SMEM for all 1024 steps. One grid barrier per step; h double-buffered.
// Thread (j = tid&3 feature, b = tid>>2 batch): full 512-length dot per gate,
// packed f32x2, no reductions needed.
// ============================================================
__global__ __launch_bounds__(THR_R, 1) void gru_scan_kernel(
    const float* __restrict__ h0,
    const float* __restrict__ whr, const float* __restrict__ whz, const float* __restrict__ whn,
    const float* __restrict__ bhr, const float* __restrict__ bhz, const float* __restrict__ bhn,
    float* __restrict__ out, float* __restrict__ hlast, int write_hlast)
{
    const int gcta  = blockIdx.x;     // 0..127
    const int fbase = gcta * 4;
    const int tid   = threadIdx.x;
    const int j     = tid & 3;        // feature within slice
    const int b     = tid >> 2;       // batch 0..63

    __shared__ __align__(16) float4 wsm[3][4][128];   // 24KB: [gate][j][kq]
    __shared__ __align__(16) float  hn_sm[BB][4];

    // Load recurrent weight slice into SMEM (once)
    {
        const float* Wt[3] = { whr, whz, whn };
#pragma unroll
        for (int g = 0; g < 3; ++g) {
            const float* Wg = Wt[g];
            for (int q = tid; q < 4 * 128; q += THR_R) {
                int jj = q >> 7, kq = q & 127;
                wsm[g][jj][kq] = *(const float4*)&Wg[(size_t)(fbase + jj) * HH + kq * 4];
            }
        }
    }
    const float br = bhr[fbase + j], bz = bhz[fbase + j], bn = bhn[fbase + j];

    // Init own slice of h (quad-of-features layout: idx = kq*256 + b*4 + c, kq = gcta)
    const int myH = gcta * 256 + b * 4 + j;
    g_H[0][myH] = h0[b * HH + fbase + j];

    unsigned mygen = 0;
    if (tid == 0) mygen = *((volatile unsigned*)&g_gen);
    grid_bar(tid, mygen);   // all slices of h0 visible

    int cur = 0;
    for (int t = 0; t < LL; ++t) {
        const float* __restrict__ Xt = g_X + (size_t)t * 3 * HH * BB;
        float xr = Xt[(0 * HH + fbase + j) * BB + b];
        float xz = Xt[(1 * HH + fbase + j) * BB + b];
        float xn = Xt[(2 * HH + fbase + j) * BB + b];
        float hold = ldcg32(&g_H[cur][myH]);

        const ulonglong2* __restrict__ hp  = (const ulonglong2*)&g_H[cur][0];
        const ulonglong2* __restrict__ wrp = (const ulonglong2*)&wsm[0][j][0];
        const ulonglong2* __restrict__ wzp = (const ulonglong2*)&wsm[1][j][0];
        const ulonglong2* __restrict__ wnp = (const ulonglong2*)&wsm[2][j][0];

        unsigned long long ar0 = 0, ar1 = 0, az0 = 0, az1 = 0, an0 = 0, an1 = 0;
#pragma unroll 8
        for (int kq = 0; kq < 128; ++kq) {
            ulonglong2 hv = ldcg128(&hp[kq * BB + b]);
            ulonglong2 w0 = wrp[kq];
            ffma2(ar0, hv.x, w0.x); ffma2(ar1, hv.y, w0.y);
            ulonglong2 w1 = wzp[kq];
            ffma2(az0, hv.x, w1.x); ffma2(az1, hv.y, w1.y);
            ulonglong2 w2 = wnp[kq];
            ffma2(an0, hv.x, w2.x); ffma2(an1, hv.y, w2.y);
        }
        float2 u0 = unpack2(ar0), u1 = unpack2(ar1);
        float dr = (u0.x + u0.y) + (u1.x + u1.y);
        u0 = unpack2(az0); u1 = unpack2(az1);
        float dz = (u0.x + u0.y) + (u1.x + u1.y);
        u0 = unpack2(an0); u1 = unpack2(an1);
        float dn = (u0.x + u0.y) + (u1.x + u1.y);

        float r = sigf(xr + dr + br);
        float z = sigf(xz + dz + bz);
        float n = tanh_f(xn + r * (dn + bn));
        float hnew = (1.0f - z) * n + z * hold;

        g_H[cur ^ 1][myH] = hnew;
        hn_sm[b][j] = hnew;
        __syncthreads();
        if (tid < BB) {
            float4 v = *(const float4*)&hn_sm[tid][0];
            *(float4*)&out[((size_t)tid * LL + t) * HH + fbase] = v;
        }
        grid_bar(tid, mygen);
        cur ^= 1;
    }

    if (write_hlast && tid < BB) {
        float4 v = *(const float4*)&hn_sm[tid][0];
        *(float4*)&hlast[(size_t)tid * HH + fbase] = v;
    }
}

// ============================================================
extern "C" void kernel_launch(void* const* d_in, const int* in_sizes, int n_in,
                              void* d_out, int out_size)
{
    const float* inputs = (const float*)d_in[0];
    const float* h0     = (const float*)d_in[1];
    const float* wir    = (const float*)d_in[2];
    const float* wiz    = (const float*)d_in[3];
    const float* win    = (const float*)d_in[4];
    const float* bir    = (const float*)d_in[5];
    const float* biz    = (const float*)d_in[6];
    const float* bin    = (const float*)d_in[7];
    const float* whr    = (const float*)d_in[8];
    const float* whz    = (const float*)d_in[9];
    const float* whn    = (const float*)d_in[10];
    const float* bhr    = (const float*)d_in[11];
    const float* bhz    = (const float*)d_in[12];
    const float* bhn    = (const float*)d_in[13];

    float* out = (float*)d_out;
    const long long n_out = (long long)BB * LL * HH;
    int write_h = ((long long)out_size >= n_out + (long long)BB * HH) ? 1 : 0;
    float* hlast = out + n_out;

    dim3 g1(LL, 12);
    input_proj_kernel<<<g1, 256>>>(inputs, wir, wiz, win, bir, biz, bin);
    gru_scan_kernel<<<GRID_R, THR_R>>>(h0, whr, whz, whn, bhr, bhz, bhn,
                                       out, hlast, write_h);
}

// round 17
// speedup vs baseline: 2.9893x; 2.9893x over previous
#include <cuda_runtime.h>
#include <cstdint>
#include <cstddef>

#define BB 64
#define LL 1024
#define II 256
#define HH 512
#define GRID_R 128
#define THR_R 128

// Scratch (device globals -- no allocation allowed in kernel_launch)
__device__ __align__(16) float g_X[(size_t)LL * 3 * HH * BB];   // [t][gate][f][b]
__device__ __align__(16) float g_H[2][HH * BB];                 // quad layout: quad q=(kq*64+b), comps j
__device__ unsigned g_flag[GRID_R * 32];                        // 128B-strided arrival flags

// ---------- packed f32x2 helpers (sm_103a) ----------
__device__ __forceinline__ unsigned long long pack2(float x, float y) {
    unsigned long long r;
    asm("mov.b64 %0, {%1,%2};" : "=l"(r) : "f"(x), "f"(y));
    return r;
}
__device__ __forceinline__ float2 unpack2(unsigned long long v) {
    float2 r;
    asm("mov.b64 {%0,%1}, %2;" : "=f"(r.x), "=f"(r.y) : "l"(v));
    return r;
}
__device__ __forceinline__ void ffma2(unsigned long long& d, unsigned long long a, unsigned long long b) {
    asm("fma.rn.f32x2 %0, %1, %2, %0;" : "+l"(d) : "l"(a), "l"(b));
}
__device__ __forceinline__ unsigned ld_acq(const unsigned* p) {
    unsigned v;
    asm volatile("ld.acquire.gpu.global.u32 %0, [%1];" : "=r"(v) : "l"(p));
    return v;
}
__device__ __forceinline__ void st_rel(unsigned* p, unsigned v) {
    asm volatile("st.release.gpu.global.u32 [%0], %1;" :: "l"(p), "r"(v));
}
__device__ __forceinline__ float ldcg32(const float* p) {
    float v;
    asm volatile("ld.global.cg.f32 %0, [%1];" : "=f"(v) : "l"(p));
    return v;
}
#define CP_ASYNC16(dst_u32, src) \
    asm volatile("cp.async.cg.shared.global [%0], [%1], 16;" :: "r"(dst_u32), "l"(src))
#define CP_COMMIT() asm volatile("cp.async.commit_group;")

__device__ __forceinline__ float sigf(float x) {
    return 1.0f / (1.0f + __expf(-x));
}
__device__ __forceinline__ float tanh_f(float x) {
    x = fminf(15.0f, fmaxf(-15.0f, x));
    float e = __expf(-2.0f * x);
    return (1.0f - e) / (1.0f + e);
}

// ============================================================
// Kernel 1: fused input projections  X[t][g][f][b] = inputs @ W_i{r,z,n}^T + b_i
// ============================================================
__global__ __launch_bounds__(256) void input_proj_kernel(
    const float* __restrict__ inp,
    const float* __restrict__ wir, const float* __restrict__ wiz, const float* __restrict__ win,
    const float* __restrict__ bir, const float* __restrict__ biz, const float* __restrict__ bin)
{
    const int t  = blockIdx.x;
    const int mt = blockIdx.y;                 // 0..11
    const int gate  = mt >> 2;
    const int frow0 = (mt & 3) * 128;
    const float* __restrict__ W  = (gate == 0) ? wir : ((gate == 1) ? wiz : win);
    const float* __restrict__ bi = (gate == 0) ? bir : ((gate == 1) ? biz : bin);

    __shared__ __align__(16) float As[32][132];   // [k][m], padded
    __shared__ __align__(16) float Bs[32][68];    // [k][n], padded

    const int tid = threadIdx.x;
    const int tx = tid & 15;   // n-group: 4 cols
    const int ty = tid >> 4;   // m-group: 8 rows (4 f32x2 pairs)

    unsigned long long acc[4][4];
#pragma unroll
    for (int p = 0; p < 4; ++p)
#pragma unroll
        for (int q = 0; q < 4; ++q) acc[p][q] = 0ull;

    const int akg  = tid & 7;    // k-quad 0..7
    const int arow = tid >> 3;   // 0..31
    const int bbi  = tid >> 2;   // 0..63
    const int bkq  = tid & 3;

    for (int kc = 0; kc < II; kc += 32) {
#pragma unroll
        for (int it = 0; it < 4; ++it) {
            int r = arow + 32 * it;
            float4 v = *(const float4*)&W[(size_t)(frow0 + r) * II + kc + akg * 4];
            As[akg * 4 + 0][r] = v.x; As[akg * 4 + 1][r] = v.y;
            As[akg * 4 + 2][r] = v.z; As[akg * 4 + 3][r] = v.w;
        }
#pragma unroll
        for (int it = 0; it < 2; ++it) {
            int k0 = bkq * 4 + it * 16;
            float4 v = *(const float4*)&inp[((size_t)bbi * LL + t) * II + kc + k0];
            Bs[k0 + 0][bbi] = v.x; Bs[k0 + 1][bbi] = v.y;
            Bs[k0 + 2][bbi] = v.z; Bs[k0 + 3][bbi] = v.w;
        }
        __syncthreads();
#pragma unroll
        for (int k = 0; k < 32; ++k) {
            const ulonglong2 a01 = *(const ulonglong2*)&As[k][ty * 8];
            const ulonglong2 a23 = *(const ulonglong2*)&As[k][ty * 8 + 4];
            const float4 bv = *(const float4*)&Bs[k][tx * 4];
            unsigned long long b0 = pack2(bv.x, bv.x);
            unsigned long long b1 = pack2(bv.y, bv.y);
            unsigned long long b2 = pack2(bv.z, bv.z);
            unsigned long long b3 = pack2(bv.w, bv.w);
            ffma2(acc[0][0], a01.x, b0); ffma2(acc[0][1], a01.x, b1);
            ffma2(acc[0][2], a01.x, b2); ffma2(acc[0][3], a01.x, b3);
            ffma2(acc[1][0], a01.y, b0); ffma2(acc[1][1], a01.y, b1);
            ffma2(acc[1][2], a01.y, b2); ffma2(acc[1][3], a01.y, b3);
            ffma2(acc[2][0], a23.x, b0); ffma2(acc[2][1], a23.x, b1);
            ffma2(acc[2][2], a23.x, b2); ffma2(acc[2][3], a23.x, b3);
            ffma2(acc[3][0], a23.y, b0); ffma2(acc[3][1], a23.y, b1);
            ffma2(acc[3][2], a23.y, b2); ffma2(acc[3][3], a23.y, b3);
        }
        __syncthreads();
    }

    float* __restrict__ Xout = g_X + (size_t)(t * 3 + gate) * HH * BB;
#pragma unroll
    for (int p = 0; p < 4; ++p) {
        float2 c0 = unpack2(acc[p][0]);
        float2 c1 = unpack2(acc[p][1]);
        float2 c2 = unpack2(acc[p][2]);
        float2 c3 = unpack2(acc[p][3]);
        int r0 = frow0 + ty * 8 + 2 * p;
        float be0 = bi[r0], be1 = bi[r0 + 1];
        float4 o0 = make_float4(c0.x + be0, c1.x + be0, c2.x + be0, c3.x + be0);
        float4 o1 = make_float4(c0.y + be1, c1.y + be1, c2.y + be1, c3.y + be1);
        *(float4*)&Xout[(size_t)r0 * BB + tx * 4]       = o0;
        *(float4*)&Xout[(size_t)(r0 + 1) * BB + tx * 4] = o1;
    }
}

// ============================================================
// Kernel 2: persistent GRU scan, SMEM-staged h, 2 batches per thread.
// 128 CTAs x 128 threads, 1 CTA/SM. CTA g owns hidden features [4g,4g+4).
// Thread (j = tid&3, bp = tid>>2) computes batches bp and bp+32 — weight LDS
// amortized 2x so the SMEM crossbar (2560 wf/step) sits below the FFMA2
// floor (3072 cyc/step). h staged via pipelined cp.async.cg (zero redundancy);
// flag-array barrier; own h carried in registers.
// ============================================================
#define WPAD 129                     // padded quads per weight row (2064B stride)
#define HQ_TOT 8192                  // h quads (128 kq * 64 b)
#define CHUNK_KQ 32                  // kq rows per chunk
#define SMEM_SCAN_BYTES (HQ_TOT * 16 + 12 * WPAD * 16 + 64 * 16)

__global__ __launch_bounds__(THR_R, 1) void gru_scan_kernel(
    const float* __restrict__ h0,
    const float* __restrict__ whr, const float* __restrict__ whz, const float* __restrict__ whn,
    const float* __restrict__ bhr, const float* __restrict__ bhz, const float* __restrict__ bhn,
    float* __restrict__ out, float* __restrict__ hlast, int write_hlast)
{
    extern __shared__ __align__(16) unsigned char smem_raw[];
    float4* hsm   = (float4*)smem_raw;            // 8192 quads = 128KB
    float4* wsm   = hsm + HQ_TOT;                 // 12*129 quads
    float4* hn_sm = wsm + 12 * WPAD;              // 64 quads

    const int gcta  = blockIdx.x;     // 0..127
    const int fbase = gcta * 4;
    const int tid   = threadIdx.x;
    const int j     = tid & 3;        // feature within slice
    const int bp    = tid >> 2;       // batch pair id 0..31
    const int b0    = bp;
    const int b1    = bp + 32;

    // Load recurrent weight slice into padded SMEM (once).
    {
        const float* Wt[3] = { whr, whz, whn };
#pragma unroll
        for (int g = 0; g < 3; ++g) {
            const float* Wg = Wt[g];
            for (int q = tid; q < 4 * 128; q += THR_R) {
                int jj = q >> 7, kq = q & 127;
                wsm[(g * 4 + jj) * WPAD + kq] =
                    *(const float4*)&Wg[(size_t)(fbase + jj) * HH + kq * 4];
            }
        }
    }
    const float br = bhr[fbase + j], bz = bhz[fbase + j], bn = bhn[fbase + j];

    // Monotonic barrier base (device globals persist across graph replays).
    __shared__ unsigned s_base;
    if (tid == 0) s_base = g_flag[gcta * 32];

    // Init own slice of h; carry own values in registers.
    const int myH0 = gcta * 256 + b0 * 4 + j;     // float index into g_H[x]
    const int myH1 = gcta * 256 + b1 * 4 + j;
    float hreg0 = h0[b0 * HH + fbase + j];
    float hreg1 = h0[b1 * HH + fbase + j];
    g_H[0][myH0] = hreg0;
    g_H[0][myH1] = hreg1;
    __threadfence();
    __syncthreads();
    const unsigned base = s_base;

    // Initial barrier: h0 slices visible everywhere.
    if (tid == 0) st_rel(&g_flag[gcta * 32], base + 1);
    while (ld_acq(&g_flag[tid * 32]) < base + 1) { }
    __syncthreads();

    const unsigned hsm_u32 = (unsigned)__cvta_generic_to_shared(hsm);
    const ulonglong2* __restrict__ wr = (const ulonglong2*)&wsm[(0 * 4 + j) * WPAD];
    const ulonglong2* __restrict__ wz = (const ulonglong2*)&wsm[(1 * 4 + j) * WPAD];
    const ulonglong2* __restrict__ wn = (const ulonglong2*)&wsm[(2 * 4 + j) * WPAD];
    const ulonglong2* __restrict__ hq = (const ulonglong2*)hsm;

    int cur = 0;
    for (int t = 0; t < LL; ++t) {
        const char* __restrict__ Hg = (const char*)&g_H[cur][0];

        // Per-step gate-input loads FIRST (L1tex queue is issue-order FIFO;
        // these 6 LDGs land ahead of the 64 cp.asyncs below).
        const float* __restrict__ Xt = g_X + (size_t)t * 3 * HH * BB;
        float xr0 = ldcg32(&Xt[(0 * HH + fbase + j) * BB + b0]);
        float xz0 = ldcg32(&Xt[(1 * HH + fbase + j) * BB + b0]);
        float xn0 = ldcg32(&Xt[(2 * HH + fbase + j) * BB + b0]);
        float xr1 = ldcg32(&Xt[(0 * HH + fbase + j) * BB + b1]);
        float xz1 = ldcg32(&Xt[(1 * HH + fbase + j) * BB + b1]);
        float xn1 = ldcg32(&Xt[(2 * HH + fbase + j) * BB + b1]);

        // Issue all 4 staged chunks (coalesced 16B/lane, L2-only path).
#pragma unroll
        for (int c = 0; c < 4; ++c) {
#pragma unroll
            for (int k = 0; k < 16; ++k) {
                int q = c * (CHUNK_KQ * 64) + k * THR_R + tid;
                CP_ASYNC16(hsm_u32 + q * 16, Hg + (size_t)q * 16);
            }
            CP_COMMIT();
        }

        unsigned long long ar0a = 0, ar0b = 0, az0a = 0, az0b = 0, an0a = 0, an0b = 0;
        unsigned long long ar1a = 0, ar1b = 0, az1a = 0, az1b = 0, an1a = 0, an1b = 0;

#define GRU_CHUNK(CIDX, WAITN)                                                  \
        asm volatile("cp.async.wait_group %0;" :: "n"(WAITN));                  \
        __syncthreads();                                                        \
        _Pragma("unroll")                                                       \
        for (int kq = (CIDX) * CHUNK_KQ; kq < (CIDX) * CHUNK_KQ + CHUNK_KQ; ++kq) { \
            ulonglong2 hv0 = hq[kq * 64 + b0];                                  \
            ulonglong2 hv1 = hq[kq * 64 + b1];                                  \
            ulonglong2 w0 = wr[kq];                                             \
            ffma2(ar0a, hv0.x, w0.x); ffma2(ar0b, hv0.y, w0.y);                 \
            ffma2(ar1a, hv1.x, w0.x); ffma2(ar1b, hv1.y, w0.y);                 \
            ulonglong2 w1 = wz[kq];                                             \
            ffma2(az0a, hv0.x, w1.x); ffma2(az0b, hv0.y, w1.y);                 \
            ffma2(az1a, hv1.x, w1.x); ffma2(az1b, hv1.y, w1.y);                 \
            ulonglong2 w2 = wn[kq];                                             \
            ffma2(an0a, hv0.x, w2.x); ffma2(an0b, hv0.y, w2.y);                 \
            ffma2(an1a, hv1.x, w2.x); ffma2(an1b, hv1.y, w2.y);                 \
        }

        GRU_CHUNK(0, 3)
        GRU_CHUNK(1, 2)
        GRU_CHUNK(2, 1)
        GRU_CHUNK(3, 0)
#undef GRU_CHUNK

        float2 u0, u1;
        u0 = unpack2(ar0a); u1 = unpack2(ar0b);
        float dr0 = (u0.x + u0.y) + (u1.x + u1.y);
        u0 = unpack2(az0a); u1 = unpack2(az0b);
        float dz0 = (u0.x + u0.y) + (u1.x + u1.y);
        u0 = unpack2(an0a); u1 = unpack2(an0b);
        float dn0 = (u0.x + u0.y) + (u1.x + u1.y);
        u0 = unpack2(ar1a); u1 = unpack2(ar1b);
        float dr1 = (u0.x + u0.y) + (u1.x + u1.y);
        u0 = unpack2(az1a); u1 = unpack2(az1b);
        float dz1 = (u0.x + u0.y) + (u1.x + u1.y);
        u0 = unpack2(an1a); u1 = unpack2(an1b);
        float dn1 = (u0.x + u0.y) + (u1.x + u1.y);

        float r0 = sigf(xr0 + dr0 + br);
        float z0 = sigf(xz0 + dz0 + bz);
        float n0 = tanh_f(xn0 + r0 * (dn0 + bn));
        float h0new = (1.0f - z0) * n0 + z0 * hreg0;
        float r1 = sigf(xr1 + dr1 + br);
        float z1 = sigf(xz1 + dz1 + bz);
        float n1 = tanh_f(xn1 + r1 * (dn1 + bn));
        float h1new = (1.0f - z1) * n1 + z1 * hreg1;
        hreg0 = h0new;
        hreg1 = h1new;

        g_H[cur ^ 1][myH0] = h0new;              // contiguous 1KB per CTA
        g_H[cur ^ 1][myH1] = h1new;
        ((float*)(hn_sm + b0))[j] = h0new;
        ((float*)(hn_sm + b1))[j] = h1new;
        __threadfence();
        __syncthreads();

        const unsigned target = base + 2 + (unsigned)t;
        if (tid == 0) st_rel(&g_flag[gcta * 32], target);
        if (tid < BB) {
            float4 v = hn_sm[tid];
            *(float4*)&out[((size_t)tid * LL + t) * HH + fbase] = v;
        }
        while (ld_acq(&g_flag[tid * 32]) < target) { }
        __syncthreads();
        cur ^= 1;
    }

    if (write_hlast && tid < BB) {
        float4 v = hn_sm[tid];
        *(float4*)&hlast[(size_t)tid * HH + fbase] = v;
    }
}

// ============================================================
extern "C" void kernel_launch(void* const* d_in, const int* in_sizes, int n_in,
                              void* d_out, int out_size)
{
    const float* inputs = (const float*)d_in[0];
    const float* h0     = (const float*)d_in[1];
    const float* wir    = (const float*)d_in[2];
    const float* wiz    = (const float*)d_in[3];
    const float* win    = (const float*)d_in[4];
    const float* bir    = (const float*)d_in[5];
    const float* biz    = (const float*)d_in[6];
    const float* bin    = (const float*)d_in[7];
    const float* whr    = (const float*)d_in[8];
    const float* whz    = (const float*)d_in[9];
    const float* whn    = (const float*)d_in[10];
    const float* bhr    = (const float*)d_in[11];
    const float* bhz    = (const float*)d_in[12];
    const float* bhn    = (const float*)d_in[13];

    float* out = (float*)d_out;
    const long long n_out = (long long)BB * LL * HH;
    int write_h = ((long long)out_size >= n_out + (long long)BB * HH) ? 1 : 0;
    float* hlast = out + n_out;

    cudaFuncSetAttribute(gru_scan_kernel,
                         cudaFuncAttributeMaxDynamicSharedMemorySize,
                         SMEM_SCAN_BYTES);

    dim3 g1(LL, 12);
    input_proj_kernel<<<g1, 256>>>(inputs, wir, wiz, win, bir, biz, bin);
    gru_scan_kernel<<<GRID_R, THR_R, SMEM_SCAN_BYTES>>>(
        h0, whr, whz, whn, bhr, bhz, bhn, out, hlast, write_h);
}